// round 15
// baseline (speedup 1.0000x reference)
#include <cuda_runtime.h>
#include <cuda_bf16.h>
#include <cstdint>
#include <cstddef>

#define NN 51200
#define GG 128

// Scratch (device-global: allocation-free rule)
__device__ __align__(16) float g_agg[NN * 64];
__device__ __align__(16) float g_gsum[GG * 64];

// ================= common helpers =================
__device__ __forceinline__ unsigned long long pack2(float a, float b) {
    unsigned long long r;
    asm("mov.b64 %0, {%1, %2};" : "=l"(r) : "f"(a), "f"(b));
    return r;
}
__device__ __forceinline__ void unpack2(unsigned long long v, float& a, float& b) {
    asm("mov.b64 {%0, %1}, %2;" : "=f"(a), "=f"(b) : "l"(v));
}
__device__ __forceinline__ unsigned long long fma2(unsigned long long a,
                                                   unsigned long long b,
                                                   unsigned long long c) {
    unsigned long long d;
    asm("fma.rn.f32x2 %0, %1, %2, %3;" : "=l"(d) : "l"(a), "l"(b), "l"(c));
    return d;
}
__device__ __forceinline__ void lds_w2(unsigned addr, unsigned long long& w0,
                                       unsigned long long& w1) {
    asm("ld.shared.v2.b64 {%0, %1}, [%2];" : "=l"(w0), "=l"(w1) : "r"(addr));
}
__device__ __forceinline__ void red_add_v4(float* p, float a, float b, float c, float d) {
    unsigned long long ga;
    asm("cvta.to.global.u64 %0, %1;" : "=l"(ga) : "l"((unsigned long long)(size_t)p));
    asm volatile("red.global.add.v4.f32 [%0], {%1,%2,%3,%4};"
                 :: "l"(ga), "f"(a), "f"(b), "f"(c), "f"(d) : "memory");
}
__device__ __forceinline__ void red_add_v2(float* p, float a, float b) {
    unsigned long long ga;
    asm("cvta.to.global.u64 %0, %1;" : "=l"(ga) : "l"((unsigned long long)(size_t)p));
    asm volatile("red.global.add.v2.f32 [%0], {%1,%2};"
                 :: "l"(ga), "f"(a), "f"(b) : "memory");
}
__device__ __forceinline__ uint32_t smem_u32(const void* p) {
    uint32_t a;
    asm("{ .reg .u64 t; cvta.to.shared.u64 t, %1; cvt.u32.u64 %0, t; }"
        : "=r"(a) : "l"(p));
    return a;
}
__device__ __forceinline__ void sts32(uint32_t addr, uint32_t v) {
    asm volatile("st.shared.b32 [%0], %1;" :: "r"(addr), "r"(v) : "memory");
}
__device__ __forceinline__ void sts_u2(uint32_t addr, uint32_t a, uint32_t b) {
    asm volatile("st.shared.v2.b32 [%0], {%1,%2};" :: "r"(addr), "r"(a), "r"(b) : "memory");
}
__device__ __forceinline__ void ldsm4(uint32_t& r0, uint32_t& r1, uint32_t& r2,
                                      uint32_t& r3, uint32_t addr) {
    asm volatile("ldmatrix.sync.aligned.m8n8.x4.shared.b16 {%0,%1,%2,%3}, [%4];"
                 : "=r"(r0), "=r"(r1), "=r"(r2), "=r"(r3) : "r"(addr));
}
// named split barriers
__device__ __forceinline__ void bar_arrive(int id, int cnt) {
    asm volatile("bar.arrive %0, %1;" :: "r"(id), "r"(cnt) : "memory");
}
__device__ __forceinline__ void bar_wait(int id, int cnt) {
    asm volatile("bar.sync %0, %1;" :: "r"(id), "r"(cnt) : "memory");
}

// warp-level bf16 MMA (baseline PTX, works on plain sm_103 target)
__device__ __forceinline__ void mma16816(float d[4], uint32_t a0, uint32_t a1,
                                         uint32_t a2, uint32_t a3,
                                         uint32_t b0, uint32_t b1) {
    asm volatile(
        "mma.sync.aligned.m16n8k16.row.col.f32.bf16.bf16.f32 "
        "{%0,%1,%2,%3}, {%4,%5,%6,%7}, {%8,%9}, {%0,%1,%2,%3};"
        : "+f"(d[0]), "+f"(d[1]), "+f"(d[2]), "+f"(d[3])
        : "r"(a0), "r"(a1), "r"(a2), "r"(a3), "r"(b0), "r"(b1));
}

// split a pair of fp32 into packed bf16x2 hi and lo
__device__ __forceinline__ uint32_t bfsplit2(float a, float b, uint32_t& lo) {
    __nv_bfloat16 ha = __float2bfloat16_rn(a), hb = __float2bfloat16_rn(b);
    float ra = a - __bfloat162float(ha);
    float rb = b - __bfloat162float(hb);
    __nv_bfloat16 la = __float2bfloat16_rn(ra), lb = __float2bfloat16_rn(rb);
    lo = ((uint32_t)__bfloat16_as_ushort(lb) << 16) | __bfloat16_as_ushort(la);
    return ((uint32_t)__bfloat16_as_ushort(hb) << 16) | __bfloat16_as_ushort(ha);
}

// ================= smem layout (bytes) =================
#define P1   400
#define P2   144
#define OFF_DST   0                          // 2 x 512B (double-buffered)
#define OFF_B1    1024
#define OFF_B2    1280
#define OFF_W1T   1536                       // hi 64*400, lo 64*400 = 51200
#define OFF_W2T   (OFF_W1T + 51200)          // hi 64*144, lo 64*144 = 18432
#define OFF_A     (OFF_W2T + 18432)          // hi 128*400, lo 128*400 = 102400
#define OFF_M     (OFF_A + 102400)           // hi 128*144, lo 128*144 = 36864
#define SMEM_TOT  (OFF_M + 36864)            // ~207KB

// barrier ids
#define BAR_AFREE 1
#define BAR_AFULL 2
#define BAR_CONS  3

// ---------- dummy kernels (ncu capture-slot alignment; keep ordering!) ----------
extern "C" __global__ void mpnn_nop1_kernel() {}
extern "C" __global__ void mpnn_nop2_kernel() {}

// ---------- kernel 0: zero scratch ----------
extern "C" __global__ void mpnn_zero_kernel() {
    float4 z = make_float4(0.f, 0.f, 0.f, 0.f);
    float4* p = (float4*)g_agg;
    int tot = NN * 64 / 4;
    int stride = gridDim.x * blockDim.x;
    for (int i = blockIdx.x * blockDim.x + threadIdx.x; i < tot; i += stride) p[i] = z;
    float4* q = (float4*)g_gsum;
    int tot2 = GG * 64 / 4;
    for (int i = blockIdx.x * blockDim.x + threadIdx.x; i < tot2; i += stride) q[i] = z;
}

// ---------- kernel 1: warp-specialized edge MLP (8 MMA warps + 8 gather warps) ----------
extern "C" __global__ void __launch_bounds__(512, 1)
mpnn_edge_mma(const float* __restrict__ h_node, const float* __restrict__ h_edge,
              const float* __restrict__ W1, const float* __restrict__ b1,
              const float* __restrict__ W2, const float* __restrict__ b2,
              const int* __restrict__ src, const int* __restrict__ dst, int E) {
    extern __shared__ __align__(16) char sm[];
    const uint32_t sb = smem_u32(sm);
    int tid = threadIdx.x;
    int lane = tid & 31;
    int warp = tid >> 5;        // 0..15  (0-7 consumers, 8-15 producers)
    int g = lane >> 2;
    int t = lane & 3;

    // ---- one-time init: biases + transposed split weights (all 512 threads) ----
    if (tid < 64) {
        ((float*)(sm + OFF_B1))[tid] = b1[tid];
        ((float*)(sm + OFF_B2))[tid] = b2[tid];
    }
    for (int i = tid; i < 192 * 64; i += 512) {
        int k = i >> 6, n = i & 63;
        float w = W1[i];
        __nv_bfloat16 hi = __float2bfloat16_rn(w);
        __nv_bfloat16 lo = __float2bfloat16_rn(w - __bfloat162float(hi));
        uint32_t off = OFF_W1T + (uint32_t)n * P1 + (uint32_t)k * 2;
        *(unsigned short*)(sm + off)             = __bfloat16_as_ushort(hi);
        *(unsigned short*)(sm + off + 64 * P1)   = __bfloat16_as_ushort(lo);
    }
    for (int i = tid; i < 64 * 64; i += 512) {
        int k = i >> 6, n = i & 63;
        float w = W2[i];
        __nv_bfloat16 hi = __float2bfloat16_rn(w);
        __nv_bfloat16 lo = __float2bfloat16_rn(w - __bfloat162float(hi));
        uint32_t off = OFF_W2T + (uint32_t)n * P2 + (uint32_t)k * 2;
        *(unsigned short*)(sm + off)             = __bfloat16_as_ushort(hi);
        *(unsigned short*)(sm + off + 64 * P2)   = __bfloat16_as_ushort(lo);
    }
    __syncthreads();

    const uint32_t W1Th = sb + OFF_W1T;
    const uint32_t W2Th = sb + OFF_W2T;
    const uint32_t Ah = sb + OFF_A,  Al = Ah + 128 * P1;
    const uint32_t Mh = sb + OFF_M,  Ml = Mh + 128 * P2;
    int* s_dst0 = (int*)(sm + OFF_DST);
    int* s_dst1 = s_dst0 + 128;

    int ntiles = (E + 127) >> 7;
    int par = 0;

    if (warp >= 8) {
        // ================= PRODUCER: gather tiles =================
        int ptid = tid - 256;   // 0..255
        for (int tIdx = blockIdx.x; tIdx < ntiles; tIdx += gridDim.x) {
            int ebase = tIdx << 7;
            int* sd = par ? s_dst1 : s_dst0;
            if (ptid < 128) {
                int e = ebase + ptid;
                sd[ptid] = (e < E) ? dst[e] : 0;
            }
            // 6144 float4 chunks / 256 threads = 24 each; 4 batches of 6
            #pragma unroll 1
            for (int b = 0; b < 4; b++) {
                const float4* ps[6];
                uint32_t offs[6];
                #pragma unroll
                for (int jj = 0; jj < 6; jj++) {
                    int idx = ptid + ((b * 6 + jj) << 8);
                    int row = idx / 48;
                    int c4 = idx - row * 48;
                    int er = ebase + row;
                    if (er >= E) er = E - 1;
                    const float4* p;
                    if (c4 < 16)      p = (const float4*)(h_node + (size_t)src[er] * 64) + c4;
                    else if (c4 < 32) p = (const float4*)(h_node + (size_t)dst[er] * 64) + (c4 - 16);
                    else              p = (const float4*)(h_edge + (size_t)er * 64) + (c4 - 32);
                    ps[jj] = p;
                    offs[jj] = (uint32_t)row * P1 + (uint32_t)c4 * 8;
                }
                float4 v[6];
                #pragma unroll
                for (int jj = 0; jj < 6; jj++) v[jj] = *ps[jj];
                #pragma unroll
                for (int jj = 0; jj < 6; jj++) {
                    uint32_t l0, l1;
                    uint32_t h0 = bfsplit2(v[jj].x, v[jj].y, l0);
                    uint32_t h1 = bfsplit2(v[jj].z, v[jj].w, l1);
                    sts_u2(Ah + offs[jj], h0, h1);
                    sts_u2(Al + offs[jj], l0, l1);
                }
            }
            bar_arrive(BAR_AFULL, 512);     // A(t) ready
            bar_wait(BAR_AFREE, 512);       // wait until consumers done reading A(t)
            par ^= 1;
        }
    } else {
        // ================= CONSUMER: m32n32 MMA warps =================
        int rowg = (warp & 3) * 32;
        int colb = (warp >> 2) * 32;
        int quad = lane >> 3, rsel = lane & 7;

        uint32_t aB0 = Ah + (uint32_t)(rowg + ((quad & 1) << 3) + rsel) * P1 + ((quad >> 1) << 4);
        uint32_t aB1 = aB0 + 16 * P1;
        uint32_t bB0 = W1Th + (uint32_t)(colb + ((quad >> 1) << 3) + rsel) * P1 + ((quad & 1) << 4);
        uint32_t bB1 = bB0 + 16 * P1;
        uint32_t a2B0 = Mh + (uint32_t)(rowg + ((quad & 1) << 3) + rsel) * P2 + ((quad >> 1) << 4);
        uint32_t a2B1 = a2B0 + 16 * P2;
        uint32_t b2B0 = W2Th + (uint32_t)(colb + ((quad >> 1) << 3) + rsel) * P2 + ((quad & 1) << 4);
        uint32_t b2B1 = b2B0 + 16 * P2;

        const float* sb1f = (const float*)(sm + OFF_B1);
        const float* sb2f = (const float*)(sm + OFF_B2);

        for (int tIdx = blockIdx.x; tIdx < ntiles; tIdx += gridDim.x) {
            int ebase = tIdx << 7;
            bar_wait(BAR_AFULL, 512);       // A(t) ready

            // ---- layer 1: 32x32 tile, 12 K-steps ----
            float acc[2][4][4];
            #pragma unroll
            for (int rh = 0; rh < 2; rh++)
                #pragma unroll
                for (int nb = 0; nb < 4; nb++)
                    #pragma unroll
                    for (int q = 0; q < 4; q++) acc[rh][nb][q] = 0.f;

            #pragma unroll 2
            for (int kk = 0; kk < 192; kk += 16) {
                uint32_t k2 = (uint32_t)kk * 2;
                uint32_t ah[8], al[8], bh[8], bl[8];
                ldsm4(ah[0], ah[1], ah[2], ah[3], aB0 + k2);
                ldsm4(ah[4], ah[5], ah[6], ah[7], aB1 + k2);
                ldsm4(al[0], al[1], al[2], al[3], aB0 + k2 + 128 * P1);
                ldsm4(al[4], al[5], al[6], al[7], aB1 + k2 + 128 * P1);
                ldsm4(bh[0], bh[1], bh[2], bh[3], bB0 + k2);
                ldsm4(bh[4], bh[5], bh[6], bh[7], bB1 + k2);
                ldsm4(bl[0], bl[1], bl[2], bl[3], bB0 + k2 + 64 * P1);
                ldsm4(bl[4], bl[5], bl[6], bl[7], bB1 + k2 + 64 * P1);
                #pragma unroll
                for (int rh = 0; rh < 2; rh++) {
                    uint32_t* A = ah + rh * 4;
                    uint32_t* AL = al + rh * 4;
                    #pragma unroll
                    for (int nb = 0; nb < 4; nb++) {
                        uint32_t b0 = bh[nb * 2], b1 = bh[nb * 2 + 1];
                        mma16816(acc[rh][nb], A[0], A[1], A[2], A[3], b0, b1);
                        mma16816(acc[rh][nb], A[0], A[1], A[2], A[3],
                                 bl[nb * 2], bl[nb * 2 + 1]);
                        mma16816(acc[rh][nb], AL[0], AL[1], AL[2], AL[3], b0, b1);
                    }
                }
            }
            bar_arrive(BAR_AFREE, 512);     // A(t) free for producers

            // ---- layer-1 epilogue: +b1, relu, re-split into M tile ----
            #pragma unroll
            for (int rh = 0; rh < 2; rh++) {
                uint32_t r0o = (uint32_t)(rowg + rh * 16 + g) * P2;
                uint32_t r1o = r0o + 8 * P2;
                #pragma unroll
                for (int nb = 0; nb < 4; nb++) {
                    int c0 = colb + nb * 8 + 2 * t;
                    float bA = sb1f[c0], bB2 = sb1f[c0 + 1];
                    float v00 = fmaxf(acc[rh][nb][0] + bA, 0.f);
                    float v01 = fmaxf(acc[rh][nb][1] + bB2, 0.f);
                    float v10 = fmaxf(acc[rh][nb][2] + bA, 0.f);
                    float v11 = fmaxf(acc[rh][nb][3] + bB2, 0.f);
                    uint32_t lo0, lo1;
                    uint32_t hi0 = bfsplit2(v00, v01, lo0);
                    uint32_t hi1 = bfsplit2(v10, v11, lo1);
                    uint32_t co = (uint32_t)c0 * 2;
                    sts32(Mh + r0o + co, hi0);
                    sts32(Ml + r0o + co, lo0);
                    sts32(Mh + r1o + co, hi1);
                    sts32(Ml + r1o + co, lo1);
                }
            }
            bar_wait(BAR_CONS, 256);        // consumer-only: M visible

            // ---- layer 2: 32x32 tile, 4 K-steps ----
            #pragma unroll
            for (int rh = 0; rh < 2; rh++)
                #pragma unroll
                for (int nb = 0; nb < 4; nb++)
                    #pragma unroll
                    for (int q = 0; q < 4; q++) acc[rh][nb][q] = 0.f;

            #pragma unroll
            for (int kk = 0; kk < 64; kk += 16) {
                uint32_t k2 = (uint32_t)kk * 2;
                uint32_t ah[8], al[8], bh[8], bl[8];
                ldsm4(ah[0], ah[1], ah[2], ah[3], a2B0 + k2);
                ldsm4(ah[4], ah[5], ah[6], ah[7], a2B1 + k2);
                ldsm4(al[0], al[1], al[2], al[3], a2B0 + k2 + 128 * P2);
                ldsm4(al[4], al[5], al[6], al[7], a2B1 + k2 + 128 * P2);
                ldsm4(bh[0], bh[1], bh[2], bh[3], b2B0 + k2);
                ldsm4(bh[4], bh[5], bh[6], bh[7], b2B1 + k2);
                ldsm4(bl[0], bl[1], bl[2], bl[3], b2B0 + k2 + 64 * P2);
                ldsm4(bl[4], bl[5], bl[6], bl[7], b2B1 + k2 + 64 * P2);
                #pragma unroll
                for (int rh = 0; rh < 2; rh++) {
                    uint32_t* A = ah + rh * 4;
                    uint32_t* AL = al + rh * 4;
                    #pragma unroll
                    for (int nb = 0; nb < 4; nb++) {
                        uint32_t b0 = bh[nb * 2], b1 = bh[nb * 2 + 1];
                        mma16816(acc[rh][nb], A[0], A[1], A[2], A[3], b0, b1);
                        mma16816(acc[rh][nb], A[0], A[1], A[2], A[3],
                                 bl[nb * 2], bl[nb * 2 + 1]);
                        mma16816(acc[rh][nb], AL[0], AL[1], AL[2], AL[3], b0, b1);
                    }
                }
            }

            // ---- layer-2 epilogue: +b2, relu, scatter-add ----
            {
                int* sd = par ? s_dst1 : s_dst0;
                #pragma unroll
                for (int rh = 0; rh < 2; rh++) {
                    int r0 = rowg + rh * 16 + g, r1 = r0 + 8;
                    bool ok0 = (ebase + r0) < E, ok1 = (ebase + r1) < E;
                    float* gp0 = g_agg + (size_t)sd[r0] * 64;
                    float* gp1 = g_agg + (size_t)sd[r1] * 64;
                    #pragma unroll
                    for (int nb = 0; nb < 4; nb++) {
                        int c0 = colb + nb * 8 + 2 * t;
                        float bA = sb2f[c0], bB2 = sb2f[c0 + 1];
                        if (ok0)
                            red_add_v2(gp0 + c0, fmaxf(acc[rh][nb][0] + bA, 0.f),
                                                 fmaxf(acc[rh][nb][1] + bB2, 0.f));
                        if (ok1)
                            red_add_v2(gp1 + c0, fmaxf(acc[rh][nb][2] + bA, 0.f),
                                                 fmaxf(acc[rh][nb][3] + bB2, 0.f));
                    }
                }
            }
            bar_wait(BAR_CONS, 256);        // M reads done before next tile overwrites
            par ^= 1;
        }
    }
}

// ---------- kernel 2: node linear + per-graph pooling (SIMT, proven) ----------
__device__ __forceinline__ void accum64(const float4* __restrict__ xp,
                                        unsigned sWb,
                                        unsigned long long acc[32]) {
    #pragma unroll 1
    for (int kk = 0; kk < 16; kk++) {
        float4 cur = xp[kk];
        unsigned base = sWb + kk * 4 * 256;
        unsigned long long xx, w0, w1;
        xx = pack2(cur.x, cur.x);
        #pragma unroll
        for (int j = 0; j < 16; j++) {
            lds_w2(base + j * 16, w0, w1);
            acc[2 * j] = fma2(xx, w0, acc[2 * j]);
            acc[2 * j + 1] = fma2(xx, w1, acc[2 * j + 1]);
        }
        xx = pack2(cur.y, cur.y);
        #pragma unroll
        for (int j = 0; j < 16; j++) {
            lds_w2(base + 256 + j * 16, w0, w1);
            acc[2 * j] = fma2(xx, w0, acc[2 * j]);
            acc[2 * j + 1] = fma2(xx, w1, acc[2 * j + 1]);
        }
        xx = pack2(cur.z, cur.z);
        #pragma unroll
        for (int j = 0; j < 16; j++) {
            lds_w2(base + 512 + j * 16, w0, w1);
            acc[2 * j] = fma2(xx, w0, acc[2 * j]);
            acc[2 * j + 1] = fma2(xx, w1, acc[2 * j + 1]);
        }
        xx = pack2(cur.w, cur.w);
        #pragma unroll
        for (int j = 0; j < 16; j++) {
            lds_w2(base + 768 + j * 16, w0, w1);
            acc[2 * j] = fma2(xx, w0, acc[2 * j]);
            acc[2 * j + 1] = fma2(xx, w1, acc[2 * j + 1]);
        }
    }
}

extern "C" __global__ void __launch_bounds__(256, 2)
mpnn_node_kernel(const float* __restrict__ Wn, const float* __restrict__ bn,
                 const int* __restrict__ ngid, int N) {
    __shared__ float sWn[64 * 64];
    __shared__ float sbn[64];
    for (int i = threadIdx.x; i < 64 * 64; i += blockDim.x) sWn[i] = Wn[i];
    if (threadIdx.x < 64) sbn[threadIdx.x] = bn[threadIdx.x];
    __syncthreads();
    unsigned sWnb = (unsigned)__cvta_generic_to_shared(sWn);

    int stride = gridDim.x * blockDim.x;
    for (int v = blockIdx.x * blockDim.x + threadIdx.x; v < N; v += stride) {
        const float4* xp = (const float4*)(g_agg + (size_t)v * 64);
        unsigned long long acc[32];
        #pragma unroll
        for (int j = 0; j < 32; j++) acc[j] = pack2(sbn[2 * j], sbn[2 * j + 1]);
        accum64(xp, sWnb, acc);

        int g = ngid[v];
        float* gp = g_gsum + (size_t)g * 64;
        #pragma unroll
        for (int q = 0; q < 16; q++) {
            float a, b, c2, d2;
            unpack2(acc[2 * q], a, b);
            unpack2(acc[2 * q + 1], c2, d2);
            red_add_v4(gp + 4 * q, a, b, c2, d2);
        }
    }
}

// ---------- kernel 3: global MLP (2 graphs per block) ----------
extern "C" __global__ void __launch_bounds__(128, 8)
mpnn_glob_kernel(const float* __restrict__ u,
                 const float* __restrict__ Wg,
                 const float* __restrict__ bg,
                 float* __restrict__ out, int G) {
    __shared__ float sx[2][192];
    int c = threadIdx.x;
    int g0 = blockIdx.x * 2;
    #pragma unroll
    for (int gg = 0; gg < 2; gg++) {
        int g = g0 + gg;
        if (g < G) {
            sx[gg][c] = u[(size_t)g * 128 + c];
            if (c < 64) sx[gg][128 + c] = g_gsum[(size_t)g * 64 + c];
        }
    }
    __syncthreads();
    #pragma unroll
    for (int gg = 0; gg < 2; gg++) {
        int g = g0 + gg;
        if (g >= G) continue;
        float acc = bg[c];
        #pragma unroll 8
        for (int k = 0; k < 192; k++)
            acc = fmaf(sx[gg][k], Wg[k * 128 + c], acc);
        out[g * 128 + c] = fmaxf(acc, 0.f);
    }
}

// ---------- launch ----------
extern "C" void kernel_launch(void* const* d_in, const int* in_sizes, int n_in,
                              void* d_out, int out_size) {
    const float* h_node = (const float*)d_in[0];
    const float* h_edge = (const float*)d_in[1];
    const float* u      = (const float*)d_in[2];
    const float* W1     = (const float*)d_in[3];
    const float* b1     = (const float*)d_in[4];
    const float* W2     = (const float*)d_in[5];
    const float* b2     = (const float*)d_in[6];
    const float* Wn     = (const float*)d_in[7];
    const float* bn     = (const float*)d_in[8];
    const float* Wg     = (const float*)d_in[9];
    const float* bg     = (const float*)d_in[10];
    const int* src      = (const int*)d_in[11];
    const int* dst      = (const int*)d_in[12];
    const int* ngid     = (const int*)d_in[13];

    int E = in_sizes[11];
    int N = in_sizes[13];
    int G = in_sizes[2] / 128;
    float* out = (float*)d_out;

    cudaFuncSetAttribute(mpnn_edge_mma,
                         cudaFuncAttributeMaxDynamicSharedMemorySize, SMEM_TOT);

    mpnn_nop1_kernel<<<1, 32>>>();
    mpnn_nop2_kernel<<<1, 32>>>();
    mpnn_zero_kernel<<<256, 256>>>();
    mpnn_edge_mma<<<148, 512, SMEM_TOT>>>(h_node, h_edge, W1, b1, W2, b2, src, dst, E);
    mpnn_node_kernel<<<304, 256>>>(Wn, bn, ngid, N);
    mpnn_glob_kernel<<<(G + 1) / 2, 128>>>(u, Wg, bg, out, G);
}

// round 16
// speedup vs baseline: 1.2994x; 1.2994x over previous
#include <cuda_runtime.h>
#include <cuda_bf16.h>
#include <cstdint>
#include <cstddef>

#define NN 51200
#define GG 128

// Scratch (device-global: allocation-free rule)
__device__ __align__(16) float g_agg[NN * 64];
__device__ __align__(16) float g_gsum[GG * 64];
__device__ __align__(16) float g_h1s[NN * 64];   // h_node @ W1[0:64] + b1
__device__ __align__(16) float g_h1d[NN * 64];   // h_node @ W1[64:128]

// ================= helpers =================
__device__ __forceinline__ void red_add_v2(float* p, float a, float b) {
    unsigned long long ga;
    asm("cvta.to.global.u64 %0, %1;" : "=l"(ga) : "l"((unsigned long long)(size_t)p));
    asm volatile("red.global.add.v2.f32 [%0], {%1,%2};"
                 :: "l"(ga), "f"(a), "f"(b) : "memory");
}
__device__ __forceinline__ uint32_t smem_u32(const void* p) {
    uint32_t a;
    asm("{ .reg .u64 t; cvta.to.shared.u64 t, %1; cvt.u32.u64 %0, t; }"
        : "=r"(a) : "l"(p));
    return a;
}
__device__ __forceinline__ void sts32(uint32_t addr, uint32_t v) {
    asm volatile("st.shared.b32 [%0], %1;" :: "r"(addr), "r"(v) : "memory");
}
__device__ __forceinline__ void sts_u2(uint32_t addr, uint32_t a, uint32_t b) {
    asm volatile("st.shared.v2.b32 [%0], {%1,%2};" :: "r"(addr), "r"(a), "r"(b) : "memory");
}
__device__ __forceinline__ void ldsm4(uint32_t& r0, uint32_t& r1, uint32_t& r2,
                                      uint32_t& r3, uint32_t addr) {
    asm volatile("ldmatrix.sync.aligned.m8n8.x4.shared.b16 {%0,%1,%2,%3}, [%4];"
                 : "=r"(r0), "=r"(r1), "=r"(r2), "=r"(r3) : "r"(addr));
}
__device__ __forceinline__ void mma16816(float d[4], uint32_t a0, uint32_t a1,
                                         uint32_t a2, uint32_t a3,
                                         uint32_t b0, uint32_t b1) {
    asm volatile(
        "mma.sync.aligned.m16n8k16.row.col.f32.bf16.bf16.f32 "
        "{%0,%1,%2,%3}, {%4,%5,%6,%7}, {%8,%9}, {%0,%1,%2,%3};"
        : "+f"(d[0]), "+f"(d[1]), "+f"(d[2]), "+f"(d[3])
        : "r"(a0), "r"(a1), "r"(a2), "r"(a3), "r"(b0), "r"(b1));
}
__device__ __forceinline__ uint32_t bfsplit2(float a, float b, uint32_t& lo) {
    __nv_bfloat16 ha = __float2bfloat16_rn(a), hb = __float2bfloat16_rn(b);
    float ra = a - __bfloat162float(ha);
    float rb = b - __bfloat162float(hb);
    __nv_bfloat16 la = __float2bfloat16_rn(ra), lb = __float2bfloat16_rn(rb);
    lo = ((uint32_t)__bfloat16_as_ushort(lb) << 16) | __bfloat16_as_ushort(la);
    return ((uint32_t)__bfloat16_as_ushort(hb) << 16) | __bfloat16_as_ushort(ha);
}

// split-store a 64-col weight matrix row-transposed into smem (pitch P2)
#define P2   144
#define HP   272

// ================= edge-kernel smem layout (bytes) =================
#define OFF_DST   0                           // 2 x 512
#define OFF_B2    1024                        // 256
#define OFF_W1C   1536                        // hi+lo 64*144*2 = 18432
#define OFF_W2T   (OFF_W1C + 18432)
#define OFF_A     (OFF_W2T + 18432)           // hi+lo 128*144*2 = 36864
#define OFF_M     (OFF_A + 36864)
#define OFF_H1S   (OFF_M + 36864)             // 128*272 = 34816 (fp32 rows)
#define OFF_H1D   (OFF_H1S + 34816)
#define SMEM_TOT  (OFF_H1D + 34816)           // 181760

// precompute kernel smem
#define PRE_B1   0
#define PRE_W    256
#define PRE_A    (PRE_W + 18432)
#define PRE_TOT  (PRE_A + 36864)              // 55552

// node kernel smem
#define ND_BN    0
#define ND_GID   256
#define ND_W     768
#define ND_A     (ND_W + 18432)
#define ND_TOT   (ND_A + 36864)               // 56064

// ---------- nop (ncu capture-slot alignment; keep edge at launch index 3) ----------
extern "C" __global__ void mpnn_nop1_kernel() {}

// ---------- zero scratch ----------
extern "C" __global__ void mpnn_zero_kernel() {
    float4 z = make_float4(0.f, 0.f, 0.f, 0.f);
    float4* p = (float4*)g_agg;
    int tot = NN * 64 / 4;
    int stride = gridDim.x * blockDim.x;
    for (int i = blockIdx.x * blockDim.x + threadIdx.x; i < tot; i += stride) p[i] = z;
    float4* q = (float4*)g_gsum;
    int tot2 = GG * 64 / 4;
    for (int i = blockIdx.x * blockDim.x + threadIdx.x; i < tot2; i += stride) q[i] = z;
}

// ---------- shared MMA building blocks ----------
// one K=64, 128x64 pass: A tile (hi at Ah, lo +128*P2), B (hi at Bt, lo +64*P2)
// warp tile m16n16: rowg=(warp&7)*16, colb=(warp>>3)*16
struct Frag { float P[2][4]; float Q[2][4]; };

__device__ __forceinline__ void mma_pass64(uint32_t aB, uint32_t bB, Frag& f) {
    #pragma unroll
    for (int jj = 0; jj < 2; jj++)
        #pragma unroll
        for (int q = 0; q < 4; q++) { f.P[jj][q] = 0.f; f.Q[jj][q] = 0.f; }
    #pragma unroll
    for (int kk = 0; kk < 64; kk += 16) {
        uint32_t k2 = (uint32_t)kk * 2;
        uint32_t ah0, ah1, ah2, ah3, al0, al1, al2, al3;
        ldsm4(ah0, ah1, ah2, ah3, aB + k2);
        ldsm4(al0, al1, al2, al3, aB + k2 + 128 * P2);
        uint32_t bh0, bh1, bh2, bh3, bl0, bl1, bl2, bl3;
        ldsm4(bh0, bh1, bh2, bh3, bB + k2);
        ldsm4(bl0, bl1, bl2, bl3, bB + k2 + 64 * P2);
        mma16816(f.P[0], ah0, ah1, ah2, ah3, bh0, bh1);
        mma16816(f.P[0], ah0, ah1, ah2, ah3, bl0, bl1);
        mma16816(f.Q[0], al0, al1, al2, al3, bh0, bh1);
        mma16816(f.P[1], ah0, ah1, ah2, ah3, bh2, bh3);
        mma16816(f.P[1], ah0, ah1, ah2, ah3, bl2, bl3);
        mma16816(f.Q[1], al0, al1, al2, al3, bh2, bh3);
    }
}

// stage a 64-row weight matrix (row-major [64][64]) split+transposed at smem off
__device__ __forceinline__ void stage_w64(char* sm, uint32_t off,
                                          const float* __restrict__ W, int tid, int nthr) {
    for (int i = tid; i < 64 * 64; i += nthr) {
        int k = i >> 6, n = i & 63;
        float w = W[i];
        __nv_bfloat16 hi = __float2bfloat16_rn(w);
        __nv_bfloat16 lo = __float2bfloat16_rn(w - __bfloat162float(hi));
        uint32_t o = off + (uint32_t)n * P2 + (uint32_t)k * 2;
        *(unsigned short*)(sm + o)            = __bfloat16_as_ushort(hi);
        *(unsigned short*)(sm + o + 64 * P2)  = __bfloat16_as_ushort(lo);
    }
}

// split a contiguous [128][64] fp32 block (base row pointer) into A tile
__device__ __forceinline__ void split_block(char* sm, uint32_t Ah, uint32_t Al,
                                            const float* __restrict__ srcp,
                                            int tid) {
    #pragma unroll
    for (int j = 0; j < 2; j++) {
        int idx = tid + (j << 10);
        int row = idx >> 4, c4 = idx & 15;
        float4 v = *((const float4*)(srcp + (size_t)row * 64) + c4);
        uint32_t l0, l1;
        uint32_t h0 = bfsplit2(v.x, v.y, l0);
        uint32_t h1 = bfsplit2(v.z, v.w, l1);
        uint32_t o = (uint32_t)row * P2 + (uint32_t)c4 * 8;
        sts_u2(Ah + o, h0, h1);
        sts_u2(Al + o, l0, l1);
    }
}

// ---------- kernel: precompute H1s/H1d = h_node @ W1[half*64 : half*64+64] ----------
extern "C" __global__ void __launch_bounds__(1024, 1)
mpnn_pre_mma(const float* __restrict__ h_node, const float* __restrict__ W1,
             const float* __restrict__ b1) {
    extern __shared__ __align__(16) char sm[];
    const uint32_t sb = smem_u32(sm);
    int tid = threadIdx.x;
    int lane = tid & 31;
    int warp = tid >> 5;
    int g = lane >> 2, t = lane & 3;
    int half = blockIdx.y;
    int base = blockIdx.x * 128;

    if (tid < 64) ((float*)(sm + PRE_B1))[tid] = (half == 0) ? b1[tid] : 0.f;
    stage_w64(sm, PRE_W, W1 + (size_t)half * 64 * 64, tid, 1024);
    split_block(sm, sb + PRE_A, sb + PRE_A + 128 * P2, h_node + (size_t)base * 64, tid);
    __syncthreads();

    int rowg = (warp & 7) * 16, colb = (warp >> 3) * 16;
    int quad = lane >> 3, rsel = lane & 7;
    uint32_t aB = sb + PRE_A + (uint32_t)(rowg + ((quad & 1) << 3) + rsel) * P2 + ((quad >> 1) << 4);
    uint32_t bB = sb + PRE_W + (uint32_t)(colb + ((quad >> 1) << 3) + rsel) * P2 + ((quad & 1) << 4);

    Frag f;
    mma_pass64(aB, bB, f);

    const float* bb = (const float*)(sm + PRE_B1);
    float* out = half ? g_h1d : g_h1s;
    #pragma unroll
    for (int jj = 0; jj < 2; jj++) {
        int c0 = colb + jj * 8 + 2 * t;
        int r0 = rowg + g, r1 = r0 + 8;
        float bA = bb[c0], bB2 = bb[c0 + 1];
        *(float2*)(out + (size_t)(base + r0) * 64 + c0) =
            make_float2(f.P[jj][0] + f.Q[jj][0] + bA, f.P[jj][1] + f.Q[jj][1] + bB2);
        *(float2*)(out + (size_t)(base + r1) * 64 + c0) =
            make_float2(f.P[jj][2] + f.Q[jj][2] + bA, f.P[jj][3] + f.Q[jj][3] + bB2);
    }
}

// ---------- kernel: edge MLP (K=64 edge part + H1 gather-add), scatter ----------
extern "C" __global__ void __launch_bounds__(1024, 1)
mpnn_edge_mma(const float* __restrict__ h_edge,
              const float* __restrict__ W1, const float* __restrict__ b2arr,
              const float* __restrict__ W2,
              const int* __restrict__ src, const int* __restrict__ dst, int E) {
    extern __shared__ __align__(16) char sm[];
    const uint32_t sb = smem_u32(sm);
    int tid = threadIdx.x;
    int lane = tid & 31;
    int warp = tid >> 5;
    int g = lane >> 2, t = lane & 3;
    int rowg = (warp & 7) * 16, colb = (warp >> 3) * 16;

    if (tid < 64) ((float*)(sm + OFF_B2))[tid] = b2arr[tid];
    stage_w64(sm, OFF_W1C, W1 + (size_t)128 * 64, tid, 1024);   // edge part of W1
    stage_w64(sm, OFF_W2T, W2, tid, 1024);

    const float* sb2f = (const float*)(sm + OFF_B2);
    int* s_dst0 = (int*)(sm + OFF_DST);
    int* s_dst1 = s_dst0 + 128;

    const uint32_t Ah = sb + OFF_A;
    const uint32_t Mh = sb + OFF_M;
    int quad = lane >> 3, rsel = lane & 7;
    uint32_t aB1 = Ah + (uint32_t)(rowg + ((quad & 1) << 3) + rsel) * P2 + ((quad >> 1) << 4);
    uint32_t bB1 = sb + OFF_W1C + (uint32_t)(colb + ((quad >> 1) << 3) + rsel) * P2 + ((quad & 1) << 4);
    uint32_t aB2 = Mh + (uint32_t)(rowg + ((quad & 1) << 3) + rsel) * P2 + ((quad >> 1) << 4);
    uint32_t bB2a = sb + OFF_W2T + (uint32_t)(colb + ((quad >> 1) << 3) + rsel) * P2 + ((quad & 1) << 4);

    int ntiles = (E + 127) >> 7;
    int buf = 0;

    // ---- gather lambda-equivalent (macro-free explicit) ----
    // done inline below; prologue gathers first tile
    auto gather = [&](int ebase, int* sdbuf) {
        if (tid < 128) {
            int e = ebase + tid;
            sdbuf[tid] = (e < E) ? dst[e] : 0;
        }
        // h_edge rows -> split A
        #pragma unroll
        for (int j = 0; j < 2; j++) {
            int idx = tid + (j << 10);
            int row = idx >> 4, c4 = idx & 15;
            int er = ebase + row; if (er >= E) er = E - 1;
            float4 v = *((const float4*)(h_edge + (size_t)er * 64) + c4);
            uint32_t l0, l1;
            uint32_t h0 = bfsplit2(v.x, v.y, l0);
            uint32_t h1 = bfsplit2(v.z, v.w, l1);
            uint32_t o = (uint32_t)row * P2 + (uint32_t)c4 * 8;
            sts_u2(Ah + o, h0, h1);
            sts_u2(Ah + 128 * P2 + o, l0, l1);
        }
        // H1s rows (fp32 raw)
        #pragma unroll
        for (int j = 0; j < 2; j++) {
            int idx = tid + (j << 10);
            int row = idx >> 4, c4 = idx & 15;
            int er = ebase + row; if (er >= E) er = E - 1;
            float4 v = *((const float4*)(g_h1s + (size_t)src[er] * 64) + c4);
            *(float4*)(sm + OFF_H1S + (size_t)row * HP + (size_t)c4 * 16) = v;
        }
        // H1d rows
        #pragma unroll
        for (int j = 0; j < 2; j++) {
            int idx = tid + (j << 10);
            int row = idx >> 4, c4 = idx & 15;
            int er = ebase + row; if (er >= E) er = E - 1;
            float4 v = *((const float4*)(g_h1d + (size_t)dst[er] * 64) + c4);
            *(float4*)(sm + OFF_H1D + (size_t)row * HP + (size_t)c4 * 16) = v;
        }
    };

    if ((int)blockIdx.x < ntiles)
        gather((int)blockIdx.x << 7, s_dst0);
    __syncthreads();

    for (int tIdx = blockIdx.x; tIdx < ntiles; tIdx += gridDim.x) {
        int ebase = tIdx << 7;

        // ---- layer 1 (K=64 edge part) ----
        Frag f;
        mma_pass64(aB1, bB1, f);

        // ---- epilogue 1: + H1s[src] + H1d[dst], relu, split into M ----
        {
            int r0 = rowg + g, r1 = r0 + 8;
            const char* hs = sm + OFF_H1S;
            const char* hd = sm + OFF_H1D;
            uint32_t r0o = (uint32_t)r0 * P2;
            uint32_t r1o = (uint32_t)r1 * P2;
            #pragma unroll
            for (int jj = 0; jj < 2; jj++) {
                int c0 = colb + jj * 8 + 2 * t;
                float2 s0 = *(const float2*)(hs + (size_t)r0 * HP + (size_t)c0 * 4);
                float2 d0 = *(const float2*)(hd + (size_t)r0 * HP + (size_t)c0 * 4);
                float2 s1 = *(const float2*)(hs + (size_t)r1 * HP + (size_t)c0 * 4);
                float2 d1 = *(const float2*)(hd + (size_t)r1 * HP + (size_t)c0 * 4);
                float v00 = fmaxf(f.P[jj][0] + f.Q[jj][0] + s0.x + d0.x, 0.f);
                float v01 = fmaxf(f.P[jj][1] + f.Q[jj][1] + s0.y + d0.y, 0.f);
                float v10 = fmaxf(f.P[jj][2] + f.Q[jj][2] + s1.x + d1.x, 0.f);
                float v11 = fmaxf(f.P[jj][3] + f.Q[jj][3] + s1.y + d1.y, 0.f);
                uint32_t lo0, lo1;
                uint32_t hi0 = bfsplit2(v00, v01, lo0);
                uint32_t hi1 = bfsplit2(v10, v11, lo1);
                uint32_t co = (uint32_t)c0 * 2;
                sts32(Mh + r0o + co, hi0);
                sts32(Mh + 128 * P2 + r0o + co, lo0);
                sts32(Mh + r1o + co, hi1);
                sts32(Mh + 128 * P2 + r1o + co, lo1);
            }
        }
        __syncthreads();   // M ready; A + H1 dead

        // ---- pipelined gather of NEXT tile (overlaps layer 2) ----
        int tNext = tIdx + gridDim.x;
        if (tNext < ntiles)
            gather(tNext << 7, buf ? s_dst0 : s_dst1);

        // ---- layer 2 ----
        mma_pass64(aB2, bB2a, f);

        // ---- epilogue 2: +b2, relu, scatter-add ----
        {
            int* sd = buf ? s_dst1 : s_dst0;
            int r0 = rowg + g, r1 = r0 + 8;
            bool ok0 = (ebase + r0) < E, ok1 = (ebase + r1) < E;
            float* gp0 = g_agg + (size_t)sd[r0] * 64;
            float* gp1 = g_agg + (size_t)sd[r1] * 64;
            #pragma unroll
            for (int jj = 0; jj < 2; jj++) {
                int c0 = colb + jj * 8 + 2 * t;
                float bA = sb2f[c0], bB2v = sb2f[c0 + 1];
                if (ok0)
                    red_add_v2(gp0 + c0, fmaxf(f.P[jj][0] + f.Q[jj][0] + bA, 0.f),
                                         fmaxf(f.P[jj][1] + f.Q[jj][1] + bB2v, 0.f));
                if (ok1)
                    red_add_v2(gp1 + c0, fmaxf(f.P[jj][2] + f.Q[jj][2] + bA, 0.f),
                                         fmaxf(f.P[jj][3] + f.Q[jj][3] + bB2v, 0.f));
            }
        }
        __syncthreads();   // next A/H1 fully written; M dead
        buf ^= 1;
    }
}

// ---------- kernel: node linear (MMA) + per-graph pooling scatter ----------
extern "C" __global__ void __launch_bounds__(1024, 1)
mpnn_node_mma(const float* __restrict__ Wn, const float* __restrict__ bn,
              const int* __restrict__ ngid) {
    extern __shared__ __align__(16) char sm[];
    const uint32_t sb = smem_u32(sm);
    int tid = threadIdx.x;
    int lane = tid & 31;
    int warp = tid >> 5;
    int g = lane >> 2, t = lane & 3;
    int base = blockIdx.x * 128;

    if (tid < 64) ((float*)(sm + ND_BN))[tid] = bn[tid];
    if (tid < 128) ((int*)(sm + ND_GID))[tid] = ngid[base + tid];
    stage_w64(sm, ND_W, Wn, tid, 1024);
    split_block(sm, sb + ND_A, sb + ND_A + 128 * P2, g_agg + (size_t)base * 64, tid);
    __syncthreads();

    int rowg = (warp & 7) * 16, colb = (warp >> 3) * 16;
    int quad = lane >> 3, rsel = lane & 7;
    uint32_t aB = sb + ND_A + (uint32_t)(rowg + ((quad & 1) << 3) + rsel) * P2 + ((quad >> 1) << 4);
    uint32_t bB = sb + ND_W + (uint32_t)(colb + ((quad >> 1) << 3) + rsel) * P2 + ((quad & 1) << 4);

    Frag f;
    mma_pass64(aB, bB, f);

    const float* bb = (const float*)(sm + ND_BN);
    const int* gid = (const int*)(sm + ND_GID);
    #pragma unroll
    for (int jj = 0; jj < 2; jj++) {
        int c0 = colb + jj * 8 + 2 * t;
        int r0 = rowg + g, r1 = r0 + 8;
        float bA = bb[c0], bB2 = bb[c0 + 1];
        red_add_v2(g_gsum + (size_t)gid[r0] * 64 + c0,
                   f.P[jj][0] + f.Q[jj][0] + bA, f.P[jj][1] + f.Q[jj][1] + bB2);
        red_add_v2(g_gsum + (size_t)gid[r1] * 64 + c0,
                   f.P[jj][2] + f.Q[jj][2] + bA, f.P[jj][3] + f.Q[jj][3] + bB2);
    }
}

// ---------- kernel: global MLP (2 graphs per block) ----------
extern "C" __global__ void __launch_bounds__(128, 8)
mpnn_glob_kernel(const float* __restrict__ u,
                 const float* __restrict__ Wg,
                 const float* __restrict__ bg,
                 float* __restrict__ out, int G) {
    __shared__ float sx[2][192];
    int c = threadIdx.x;
    int g0 = blockIdx.x * 2;
    #pragma unroll
    for (int gg = 0; gg < 2; gg++) {
        int g = g0 + gg;
        if (g < G) {
            sx[gg][c] = u[(size_t)g * 128 + c];
            if (c < 64) sx[gg][128 + c] = g_gsum[(size_t)g * 64 + c];
        }
    }
    __syncthreads();
    #pragma unroll
    for (int gg = 0; gg < 2; gg++) {
        int g = g0 + gg;
        if (g >= G) continue;
        float acc = bg[c];
        #pragma unroll 8
        for (int k = 0; k < 192; k++)
            acc = fmaf(sx[gg][k], Wg[k * 128 + c], acc);
        out[g * 128 + c] = fmaxf(acc, 0.f);
    }
}

// ---------- launch ----------
extern "C" void kernel_launch(void* const* d_in, const int* in_sizes, int n_in,
                              void* d_out, int out_size) {
    const float* h_node = (const float*)d_in[0];
    const float* h_edge = (const float*)d_in[1];
    const float* u      = (const float*)d_in[2];
    const float* W1     = (const float*)d_in[3];
    const float* b1     = (const float*)d_in[4];
    const float* W2     = (const float*)d_in[5];
    const float* b2     = (const float*)d_in[6];
    const float* Wn     = (const float*)d_in[7];
    const float* bn     = (const float*)d_in[8];
    const float* Wg     = (const float*)d_in[9];
    const float* bg     = (const float*)d_in[10];
    const int* src      = (const int*)d_in[11];
    const int* dst      = (const int*)d_in[12];
    const int* ngid     = (const int*)d_in[13];

    int E = in_sizes[11];
    int N = in_sizes[13];
    int G = in_sizes[2] / 128;
    float* out = (float*)d_out;

    cudaFuncSetAttribute(mpnn_edge_mma,
                         cudaFuncAttributeMaxDynamicSharedMemorySize, SMEM_TOT);
    cudaFuncSetAttribute(mpnn_pre_mma,
                         cudaFuncAttributeMaxDynamicSharedMemorySize, PRE_TOT);
    cudaFuncSetAttribute(mpnn_node_mma,
                         cudaFuncAttributeMaxDynamicSharedMemorySize, ND_TOT);

    int nblk = N / 128;   // 400

    mpnn_nop1_kernel<<<1, 32>>>();
    mpnn_zero_kernel<<<256, 256>>>();
    mpnn_pre_mma<<<dim3(nblk, 2), 1024, PRE_TOT>>>(h_node, W1, b1);
    mpnn_edge_mma<<<148, 1024, SMEM_TOT>>>(h_edge, W1, b2, W2, src, dst, E);
    mpnn_node_mma<<<nblk, 1024, ND_TOT>>>(Wn, bn, ngid);
    mpnn_glob_kernel<<<(G + 1) / 2, 128>>>(u, Wg, bg, out, G);
}

// round 17
// speedup vs baseline: 1.7868x; 1.3751x over previous
#include <cuda_runtime.h>
#include <cuda_bf16.h>
#include <cstdint>
#include <cstddef>

#define NN 51200
#define GG 128

// Scratch (device-global: allocation-free rule)
__device__ __align__(16) float g_agg[NN * 64];
__device__ __align__(16) float g_gsum[GG * 64];
__device__ __align__(16) float g_h1s[NN * 64];   // h_node @ W1[0:64] + b1
__device__ __align__(16) float g_h1d[NN * 64];   // h_node @ W1[64:128]

// ================= helpers =================
__device__ __forceinline__ void red_add_v2(float* p, float a, float b) {
    unsigned long long ga;
    asm("cvta.to.global.u64 %0, %1;" : "=l"(ga) : "l"((unsigned long long)(size_t)p));
    asm volatile("red.global.add.v2.f32 [%0], {%1,%2};"
                 :: "l"(ga), "f"(a), "f"(b) : "memory");
}
__device__ __forceinline__ uint32_t smem_u32(const void* p) {
    uint32_t a;
    asm("{ .reg .u64 t; cvta.to.shared.u64 t, %1; cvt.u32.u64 %0, t; }"
        : "=r"(a) : "l"(p));
    return a;
}
__device__ __forceinline__ void sts32(uint32_t addr, uint32_t v) {
    asm volatile("st.shared.b32 [%0], %1;" :: "r"(addr), "r"(v) : "memory");
}
__device__ __forceinline__ void sts_u2(uint32_t addr, uint32_t a, uint32_t b) {
    asm volatile("st.shared.v2.b32 [%0], {%1,%2};" :: "r"(addr), "r"(a), "r"(b) : "memory");
}
__device__ __forceinline__ void ldsm4(uint32_t& r0, uint32_t& r1, uint32_t& r2,
                                      uint32_t& r3, uint32_t addr) {
    asm volatile("ldmatrix.sync.aligned.m8n8.x4.shared.b16 {%0,%1,%2,%3}, [%4];"
                 : "=r"(r0), "=r"(r1), "=r"(r2), "=r"(r3) : "r"(addr));
}
__device__ __forceinline__ void mma16816(float d[4], uint32_t a0, uint32_t a1,
                                         uint32_t a2, uint32_t a3,
                                         uint32_t b0, uint32_t b1) {
    asm volatile(
        "mma.sync.aligned.m16n8k16.row.col.f32.bf16.bf16.f32 "
        "{%0,%1,%2,%3}, {%4,%5,%6,%7}, {%8,%9}, {%0,%1,%2,%3};"
        : "+f"(d[0]), "+f"(d[1]), "+f"(d[2]), "+f"(d[3])
        : "r"(a0), "r"(a1), "r"(a2), "r"(a3), "r"(b0), "r"(b1));
}
__device__ __forceinline__ uint32_t bfsplit2(float a, float b, uint32_t& lo) {
    __nv_bfloat16 ha = __float2bfloat16_rn(a), hb = __float2bfloat16_rn(b);
    float ra = a - __bfloat162float(ha);
    float rb = b - __bfloat162float(hb);
    __nv_bfloat16 la = __float2bfloat16_rn(ra), lb = __float2bfloat16_rn(rb);
    lo = ((uint32_t)__bfloat16_as_ushort(lb) << 16) | __bfloat16_as_ushort(la);
    return ((uint32_t)__bfloat16_as_ushort(hb) << 16) | __bfloat16_as_ushort(ha);
}

#define P2   144

// ================= edge-kernel smem layout (bytes) =================
#define OFF_SRC   0                           // 2 x 512
#define OFF_DST   1024                        // 2 x 512
#define OFF_B2    2048                        // 256
#define OFF_W1C   2560                        // hi+lo 64*144*2 = 18432
#define OFF_W2T   (OFF_W1C + 18432)
#define OFF_A     (OFF_W2T + 18432)           // hi+lo 128*144*2 = 36864
#define OFF_M     (OFF_A + 36864)
#define SMEM_TOT  (OFF_M + 36864)             // 113152

// precompute kernel smem
#define PRE_B1   0
#define PRE_W    256
#define PRE_A    (PRE_W + 18432)
#define PRE_TOT  (PRE_A + 36864)              // 55552

// node kernel smem
#define ND_BN    0
#define ND_GID   256
#define ND_W     768
#define ND_A     (ND_W + 18432)
#define ND_TOT   (ND_A + 36864)               // 56064

// ---------- nop (ncu capture-slot alignment; keep edge at launch index 3) ----------
extern "C" __global__ void mpnn_nop1_kernel() {}

// ---------- zero scratch ----------
extern "C" __global__ void mpnn_zero_kernel() {
    float4 z = make_float4(0.f, 0.f, 0.f, 0.f);
    float4* p = (float4*)g_agg;
    int tot = NN * 64 / 4;
    int stride = gridDim.x * blockDim.x;
    for (int i = blockIdx.x * blockDim.x + threadIdx.x; i < tot; i += stride) p[i] = z;
    float4* q = (float4*)g_gsum;
    int tot2 = GG * 64 / 4;
    for (int i = blockIdx.x * blockDim.x + threadIdx.x; i < tot2; i += stride) q[i] = z;
}

// ---------- shared MMA building blocks ----------
struct Frag { float P[2][4]; float Q[2][4]; };

__device__ __forceinline__ void mma_pass64(uint32_t aB, uint32_t bB, Frag& f) {
    #pragma unroll
    for (int jj = 0; jj < 2; jj++)
        #pragma unroll
        for (int q = 0; q < 4; q++) { f.P[jj][q] = 0.f; f.Q[jj][q] = 0.f; }
    #pragma unroll
    for (int kk = 0; kk < 64; kk += 16) {
        uint32_t k2 = (uint32_t)kk * 2;
        uint32_t ah0, ah1, ah2, ah3, al0, al1, al2, al3;
        ldsm4(ah0, ah1, ah2, ah3, aB + k2);
        ldsm4(al0, al1, al2, al3, aB + k2 + 128 * P2);
        uint32_t bh0, bh1, bh2, bh3, bl0, bl1, bl2, bl3;
        ldsm4(bh0, bh1, bh2, bh3, bB + k2);
        ldsm4(bl0, bl1, bl2, bl3, bB + k2 + 64 * P2);
        mma16816(f.P[0], ah0, ah1, ah2, ah3, bh0, bh1);
        mma16816(f.P[0], ah0, ah1, ah2, ah3, bl0, bl1);
        mma16816(f.Q[0], al0, al1, al2, al3, bh0, bh1);
        mma16816(f.P[1], ah0, ah1, ah2, ah3, bh2, bh3);
        mma16816(f.P[1], ah0, ah1, ah2, ah3, bl2, bl3);
        mma16816(f.Q[1], al0, al1, al2, al3, bh2, bh3);
    }
}

__device__ __forceinline__ void stage_w64(char* sm, uint32_t off,
                                          const float* __restrict__ W, int tid, int nthr) {
    for (int i = tid; i < 64 * 64; i += nthr) {
        int k = i >> 6, n = i & 63;
        float w = W[i];
        __nv_bfloat16 hi = __float2bfloat16_rn(w);
        __nv_bfloat16 lo = __float2bfloat16_rn(w - __bfloat162float(hi));
        uint32_t o = off + (uint32_t)n * P2 + (uint32_t)k * 2;
        *(unsigned short*)(sm + o)            = __bfloat16_as_ushort(hi);
        *(unsigned short*)(sm + o + 64 * P2)  = __bfloat16_as_ushort(lo);
    }
}

__device__ __forceinline__ void split_block(char* sm, uint32_t Ah, uint32_t Al,
                                            const float* __restrict__ srcp,
                                            int tid) {
    #pragma unroll
    for (int j = 0; j < 2; j++) {
        int idx = tid + (j << 10);
        int row = idx >> 4, c4 = idx & 15;
        float4 v = *((const float4*)(srcp + (size_t)row * 64) + c4);
        uint32_t l0, l1;
        uint32_t h0 = bfsplit2(v.x, v.y, l0);
        uint32_t h1 = bfsplit2(v.z, v.w, l1);
        uint32_t o = (uint32_t)row * P2 + (uint32_t)c4 * 8;
        sts_u2(Ah + o, h0, h1);
        sts_u2(Al + o, l0, l1);
    }
}

// ---------- kernel: precompute H1s/H1d = h_node @ W1[half*64 : half*64+64] ----------
extern "C" __global__ void __launch_bounds__(1024, 1)
mpnn_pre_mma(const float* __restrict__ h_node, const float* __restrict__ W1,
             const float* __restrict__ b1) {
    extern __shared__ __align__(16) char sm[];
    const uint32_t sb = smem_u32(sm);
    int tid = threadIdx.x;
    int lane = tid & 31;
    int warp = tid >> 5;
    int g = lane >> 2, t = lane & 3;
    int half = blockIdx.y;
    int base = blockIdx.x * 128;

    if (tid < 64) ((float*)(sm + PRE_B1))[tid] = (half == 0) ? b1[tid] : 0.f;
    stage_w64(sm, PRE_W, W1 + (size_t)half * 64 * 64, tid, 1024);
    split_block(sm, sb + PRE_A, sb + PRE_A + 128 * P2, h_node + (size_t)base * 64, tid);
    __syncthreads();

    int rowg = (warp & 7) * 16, colb = (warp >> 3) * 16;
    int quad = lane >> 3, rsel = lane & 7;
    uint32_t aB = sb + PRE_A + (uint32_t)(rowg + ((quad & 1) << 3) + rsel) * P2 + ((quad >> 1) << 4);
    uint32_t bB = sb + PRE_W + (uint32_t)(colb + ((quad >> 1) << 3) + rsel) * P2 + ((quad & 1) << 4);

    Frag f;
    mma_pass64(aB, bB, f);

    const float* bb = (const float*)(sm + PRE_B1);
    float* out = half ? g_h1d : g_h1s;
    #pragma unroll
    for (int jj = 0; jj < 2; jj++) {
        int c0 = colb + jj * 8 + 2 * t;
        int r0 = rowg + g, r1 = r0 + 8;
        float bA = bb[c0], bB2 = bb[c0 + 1];
        *(float2*)(out + (size_t)(base + r0) * 64 + c0) =
            make_float2(f.P[jj][0] + f.Q[jj][0] + bA, f.P[jj][1] + f.Q[jj][1] + bB2);
        *(float2*)(out + (size_t)(base + r1) * 64 + c0) =
            make_float2(f.P[jj][2] + f.Q[jj][2] + bA, f.P[jj][3] + f.Q[jj][3] + bB2);
    }
}

// ---------- kernel: edge MLP (K=64 edge part + direct H1 gather-add), scatter ----------
extern "C" __global__ void __launch_bounds__(1024, 1)
mpnn_edge_mma(const float* __restrict__ h_edge,
              const float* __restrict__ W1, const float* __restrict__ b2arr,
              const float* __restrict__ W2,
              const int* __restrict__ src, const int* __restrict__ dst, int E) {
    extern __shared__ __align__(16) char sm[];
    const uint32_t sb = smem_u32(sm);
    int tid = threadIdx.x;
    int lane = tid & 31;
    int warp = tid >> 5;
    int g = lane >> 2, t = lane & 3;
    int rowg = (warp & 7) * 16, colb = (warp >> 3) * 16;

    if (tid < 64) ((float*)(sm + OFF_B2))[tid] = b2arr[tid];
    stage_w64(sm, OFF_W1C, W1 + (size_t)128 * 64, tid, 1024);   // edge part of W1
    stage_w64(sm, OFF_W2T, W2, tid, 1024);

    const float* sb2f = (const float*)(sm + OFF_B2);
    int* s_src0 = (int*)(sm + OFF_SRC);
    int* s_src1 = s_src0 + 128;
    int* s_dst0 = (int*)(sm + OFF_DST);
    int* s_dst1 = s_dst0 + 128;

    const uint32_t Ah = sb + OFF_A;
    const uint32_t Mh = sb + OFF_M;
    int quad = lane >> 3, rsel = lane & 7;
    uint32_t aB1 = Ah + (uint32_t)(rowg + ((quad & 1) << 3) + rsel) * P2 + ((quad >> 1) << 4);
    uint32_t bB1 = sb + OFF_W1C + (uint32_t)(colb + ((quad >> 1) << 3) + rsel) * P2 + ((quad & 1) << 4);
    uint32_t aB2 = Mh + (uint32_t)(rowg + ((quad & 1) << 3) + rsel) * P2 + ((quad >> 1) << 4);
    uint32_t bB2a = sb + OFF_W2T + (uint32_t)(colb + ((quad >> 1) << 3) + rsel) * P2 + ((quad & 1) << 4);

    int ntiles = (E + 127) >> 7;
    int buf = 0;

    // gather: stage indices + split h_edge rows into A (light now)
    auto gather = [&](int ebase, int* ssbuf, int* sdbuf) {
        if (tid < 128) {
            int e = ebase + tid;
            ssbuf[tid] = (e < E) ? src[e] : 0;
        } else if (tid < 256) {
            int e = ebase + (tid - 128);
            sdbuf[tid - 128] = (e < E) ? dst[e] : 0;
        }
        #pragma unroll
        for (int j = 0; j < 2; j++) {
            int idx = tid + (j << 10);
            int row = idx >> 4, c4 = idx & 15;
            int er = ebase + row; if (er >= E) er = E - 1;
            float4 v = *((const float4*)(h_edge + (size_t)er * 64) + c4);
            uint32_t l0, l1;
            uint32_t h0 = bfsplit2(v.x, v.y, l0);
            uint32_t h1 = bfsplit2(v.z, v.w, l1);
            uint32_t o = (uint32_t)row * P2 + (uint32_t)c4 * 8;
            sts_u2(Ah + o, h0, h1);
            sts_u2(Ah + 128 * P2 + o, l0, l1);
        }
    };

    if ((int)blockIdx.x < ntiles)
        gather((int)blockIdx.x << 7, s_src0, s_dst0);
    __syncthreads();

    for (int tIdx = blockIdx.x; tIdx < ntiles; tIdx += gridDim.x) {
        int ebase = tIdx << 7;
        int* cs = buf ? s_src1 : s_src0;   // current-tile index buffers
        int* cd = buf ? s_dst1 : s_dst0;

        // ---- layer 1 (K=64 edge part) ----
        Frag f;
        mma_pass64(aB1, bB1, f);

        // ---- epilogue 1: + H1s[src] + H1d[dst] (direct from L2), relu, split into M ----
        {
            int r0 = rowg + g, r1 = r0 + 8;
            int is0 = cs[r0], is1 = cs[r1];
            int id0 = cd[r0], id1 = cd[r1];
            // batched independent loads (MLP=16)
            float2 hs0[2], hs1[2], hd0[2], hd1[2];
            #pragma unroll
            for (int jj = 0; jj < 2; jj++) {
                int c0 = colb + jj * 8 + 2 * t;
                hs0[jj] = *(const float2*)(g_h1s + (size_t)is0 * 64 + c0);
                hs1[jj] = *(const float2*)(g_h1s + (size_t)is1 * 64 + c0);
                hd0[jj] = *(const float2*)(g_h1d + (size_t)id0 * 64 + c0);
                hd1[jj] = *(const float2*)(g_h1d + (size_t)id1 * 64 + c0);
            }
            uint32_t r0o = (uint32_t)r0 * P2;
            uint32_t r1o = (uint32_t)r1 * P2;
            #pragma unroll
            for (int jj = 0; jj < 2; jj++) {
                int c0 = colb + jj * 8 + 2 * t;
                float v00 = fmaxf(f.P[jj][0] + f.Q[jj][0] + hs0[jj].x + hd0[jj].x, 0.f);
                float v01 = fmaxf(f.P[jj][1] + f.Q[jj][1] + hs0[jj].y + hd0[jj].y, 0.f);
                float v10 = fmaxf(f.P[jj][2] + f.Q[jj][2] + hs1[jj].x + hd1[jj].x, 0.f);
                float v11 = fmaxf(f.P[jj][3] + f.Q[jj][3] + hs1[jj].y + hd1[jj].y, 0.f);
                uint32_t lo0, lo1;
                uint32_t hi0 = bfsplit2(v00, v01, lo0);
                uint32_t hi1 = bfsplit2(v10, v11, lo1);
                uint32_t co = (uint32_t)c0 * 2;
                sts32(Mh + r0o + co, hi0);
                sts32(Mh + 128 * P2 + r0o + co, lo0);
                sts32(Mh + r1o + co, hi1);
                sts32(Mh + 128 * P2 + r1o + co, lo1);
            }
        }
        __syncthreads();   // M ready; A + index bufs of next slot free

        // ---- pipelined gather of NEXT tile (overlaps layer 2) ----
        int tNext = tIdx + gridDim.x;
        if (tNext < ntiles)
            gather(tNext << 7, buf ? s_src0 : s_src1, buf ? s_dst0 : s_dst1);

        // ---- layer 2 ----
        mma_pass64(aB2, bB2a, f);

        // ---- epilogue 2: +b2, relu, scatter-add ----
        {
            int r0 = rowg + g, r1 = r0 + 8;
            bool ok0 = (ebase + r0) < E, ok1 = (ebase + r1) < E;
            float* gp0 = g_agg + (size_t)cd[r0] * 64;
            float* gp1 = g_agg + (size_t)cd[r1] * 64;
            #pragma unroll
            for (int jj = 0; jj < 2; jj++) {
                int c0 = colb + jj * 8 + 2 * t;
                float bA = sb2f[c0], bB2v = sb2f[c0 + 1];
                if (ok0)
                    red_add_v2(gp0 + c0, fmaxf(f.P[jj][0] + f.Q[jj][0] + bA, 0.f),
                                         fmaxf(f.P[jj][1] + f.Q[jj][1] + bB2v, 0.f));
                if (ok1)
                    red_add_v2(gp1 + c0, fmaxf(f.P[jj][2] + f.Q[jj][2] + bA, 0.f),
                                         fmaxf(f.P[jj][3] + f.Q[jj][3] + bB2v, 0.f));
            }
        }
        __syncthreads();   // next A fully written; M dead
        buf ^= 1;
    }
}

// ---------- kernel: node linear (MMA) + per-graph pooling scatter ----------
extern "C" __global__ void __launch_bounds__(1024, 1)
mpnn_node_mma(const float* __restrict__ Wn, const float* __restrict__ bn,
              const int* __restrict__ ngid) {
    extern __shared__ __align__(16) char sm[];
    const uint32_t sb = smem_u32(sm);
    int tid = threadIdx.x;
    int lane = tid & 31;
    int warp = tid >> 5;
    int g = lane >> 2, t = lane & 3;
    int base = blockIdx.x * 128;

    if (tid < 64) ((float*)(sm + ND_BN))[tid] = bn[tid];
    if (tid < 128) ((int*)(sm + ND_GID))[tid] = ngid[base + tid];
    stage_w64(sm, ND_W, Wn, tid, 1024);
    split_block(sm, sb + ND_A, sb + ND_A + 128 * P2, g_agg + (size_t)base * 64, tid);
    __syncthreads();

    int rowg = (warp & 7) * 16, colb = (warp >> 3) * 16;
    int quad = lane >> 3, rsel = lane & 7;
    uint32_t aB = sb + ND_A + (uint32_t)(rowg + ((quad & 1) << 3) + rsel) * P2 + ((quad >> 1) << 4);
    uint32_t bB = sb + ND_W + (uint32_t)(colb + ((quad >> 1) << 3) + rsel) * P2 + ((quad & 1) << 4);

    Frag f;
    mma_pass64(aB, bB, f);

    const float* bb = (const float*)(sm + ND_BN);
    const int* gid = (const int*)(sm + ND_GID);
    #pragma unroll
    for (int jj = 0; jj < 2; jj++) {
        int c0 = colb + jj * 8 + 2 * t;
        int r0 = rowg + g, r1 = r0 + 8;
        float bA = bb[c0], bB2 = bb[c0 + 1];
        red_add_v2(g_gsum + (size_t)gid[r0] * 64 + c0,
                   f.P[jj][0] + f.Q[jj][0] + bA, f.P[jj][1] + f.Q[jj][1] + bB2);
        red_add_v2(g_gsum + (size_t)gid[r1] * 64 + c0,
                   f.P[jj][2] + f.Q[jj][2] + bA, f.P[jj][3] + f.Q[jj][3] + bB2);
    }
}

// ---------- kernel: global MLP (2 graphs per block) ----------
extern "C" __global__ void __launch_bounds__(128, 8)
mpnn_glob_kernel(const float* __restrict__ u,
                 const float* __restrict__ Wg,
                 const float* __restrict__ bg,
                 float* __restrict__ out, int G) {
    __shared__ float sx[2][192];
    int c = threadIdx.x;
    int g0 = blockIdx.x * 2;
    #pragma unroll
    for (int gg = 0; gg < 2; gg++) {
        int g = g0 + gg;
        if (g < G) {
            sx[gg][c] = u[(size_t)g * 128 + c];
            if (c < 64) sx[gg][128 + c] = g_gsum[(size_t)g * 64 + c];
        }
    }
    __syncthreads();
    #pragma unroll
    for (int gg = 0; gg < 2; gg++) {
        int g = g0 + gg;
        if (g >= G) continue;
        float acc = bg[c];
        #pragma unroll 8
        for (int k = 0; k < 192; k++)
            acc = fmaf(sx[gg][k], Wg[k * 128 + c], acc);
        out[g * 128 + c] = fmaxf(acc, 0.f);
    }
}

// ---------- launch ----------
extern "C" void kernel_launch(void* const* d_in, const int* in_sizes, int n_in,
                              void* d_out, int out_size) {
    const float* h_node = (const float*)d_in[0];
    const float* h_edge = (const float*)d_in[1];
    const float* u      = (const float*)d_in[2];
    const float* W1     = (const float*)d_in[3];
    const float* b1     = (const float*)d_in[4];
    const float* W2     = (const float*)d_in[5];
    const float* b2     = (const float*)d_in[6];
    const float* Wn     = (const float*)d_in[7];
    const float* bn     = (const float*)d_in[8];
    const float* Wg     = (const float*)d_in[9];
    const float* bg     = (const float*)d_in[10];
    const int* src      = (const int*)d_in[11];
    const int* dst      = (const int*)d_in[12];
    const int* ngid     = (const int*)d_in[13];

    int E = in_sizes[11];
    int N = in_sizes[13];
    int G = in_sizes[2] / 128;
    float* out = (float*)d_out;

    cudaFuncSetAttribute(mpnn_edge_mma,
                         cudaFuncAttributeMaxDynamicSharedMemorySize, SMEM_TOT);
    cudaFuncSetAttribute(mpnn_pre_mma,
                         cudaFuncAttributeMaxDynamicSharedMemorySize, PRE_TOT);
    cudaFuncSetAttribute(mpnn_node_mma,
                         cudaFuncAttributeMaxDynamicSharedMemorySize, ND_TOT);

    int nblk = N / 128;   // 400

    mpnn_nop1_kernel<<<1, 32>>>();
    mpnn_zero_kernel<<<256, 256>>>();
    mpnn_pre_mma<<<dim3(nblk, 2), 1024, PRE_TOT>>>(h_node, W1, b1);
    mpnn_edge_mma<<<148, 1024, SMEM_TOT>>>(h_edge, W1, b2, W2, src, dst, E);
    mpnn_node_mma<<<nblk, 1024, ND_TOT>>>(Wn, bn, ngid);
    mpnn_glob_kernel<<<(G + 1) / 2, 128>>>(u, Wg, bg, out, G);
}